// round 13
// baseline (speedup 1.0000x reference)
#include <cuda_runtime.h>
#include <cuda_fp16.h>
#include <cstdint>

// ---------------------------------------------------------------------------
// DyResConv inference, batch=1 — fp16 mma.sync m16n8k16 implicit GEMM
//   GEMM: C[768 x 14400] = W2[768 x 6912] * im2col(x),  k = tap*768 + ic
// R10: 64x64 warp tiles (2x2 warps, 128 thr) to halve A-fragment duplication
//      on the smem crossbar (co-bottleneck at 131KB/iter vs 128B/cyc).
// ---------------------------------------------------------------------------

#define CCH 768
#define SQZ 48
#define HW_ 14400
#define KTOT 6912
#define NI   108            // 6912 / 64
#define NHR  122            // padded rows/cols in pixel space
#define NHPL (NHR * NHR)    // 14884 padded pixels

// scratch (device globals; no allocation allowed)
__device__ float d_sum5[CCH * 25];
__device__ float d_sum3[CCH * 9];
__device__ float d_route[2304];
__device__ float d_h1g[SQZ * 25];
__device__ int   d_sync;
__device__ __half d_w2f[CCH * KTOT];          // weights in mma-fragment order
__device__ __half d_xnh[(size_t)NHPL * CCH];  // padded x, NHWC halves (22.9MB)

__constant__ float c_M35[5][3] = {
    { 1.096f, -0.096f,  0.000f},
    { 0.612f,  0.460f, -0.072f},
    { 0.000f,  1.000f,  0.000f},
    {-0.072f,  0.460f,  0.612f},
    { 0.000f, -0.096f,  1.096f}
};

// ---------------------------------------------------------------------------
// 1) fused transpose (NCHW f32 -> padded NHWC f16) + pooling via shfl trees.
// ---------------------------------------------------------------------------
__global__ void transpool_kernel(const float* __restrict__ x) {
    const int cg = blockIdx.x;
    const int pg = blockIdx.y;
    const int tid = threadIdx.x;
    const int warp = tid >> 5, lane = tid & 31;
    const int r0 = pg * 10;

    __shared__ __half sb[120 * 40];
    __shared__ float bins5[32][2][5];
    __shared__ float bins3[32][2][3];

    for (int i = tid; i < 32 * 10; i += 256) bins5[i / 10][(i % 10) / 5][i % 5] = 0.f;
    for (int i = tid; i < 32 * 6; i += 256) bins3[i / 6][(i % 6) / 3][i % 3] = 0.f;

    {
        int id = pg * 256 + tid;
        if (id < 484 * 4) {
            int b = id >> 2, chunk = id & 3;
            int prow, pcol;
            if (b < 122)      { prow = 0;        pcol = b; }
            else if (b < 244) { prow = 121;      pcol = b - 122; }
            else if (b < 364) { prow = b - 243;  pcol = 0; }
            else              { prow = b - 363;  pcol = 121; }
            *(uint4*)(d_xnh + ((size_t)prow * NHR + pcol) * CCH + cg * 32 + chunk * 8) =
                make_uint4(0u, 0u, 0u, 0u);
        }
    }
    __syncthreads();

    const int rbb5 = r0 / 24, rbb3 = r0 / 40;

    for (int r = 0; r < 10; r++) {
        const int gr = r0 + r;
        const int rb5l = gr / 24 - rbb5;
        const int rb3l = gr / 40 - rbb3;
#pragma unroll
        for (int cidx = 0; cidx < 4; cidx++) {
            int c_l = warp + cidx * 8;
            const float* xr = x + (size_t)(cg * 32 + c_l) * HW_ + gr * 120;
            float lb5[5] = {0.f, 0.f, 0.f, 0.f, 0.f};
            float lb3[3] = {0.f, 0.f, 0.f};
#pragma unroll
            for (int k = 0; k < 4; k++) {
                int px = lane + k * 32;
                if (px < 120) {
                    float v = xr[px];
                    sb[px * 40 + c_l] = __float2half(v);
                    lb5[px / 24] += v;
                    lb3[px / 40] += v;
                }
            }
#pragma unroll
            for (int o = 16; o > 0; o >>= 1) {
#pragma unroll
                for (int b = 0; b < 5; b++)
                    lb5[b] += __shfl_down_sync(0xFFFFFFFFu, lb5[b], o);
#pragma unroll
                for (int b = 0; b < 3; b++)
                    lb3[b] += __shfl_down_sync(0xFFFFFFFFu, lb3[b], o);
            }
            if (lane == 0) {
#pragma unroll
                for (int b = 0; b < 5; b++) bins5[c_l][rb5l][b] += lb5[b];
#pragma unroll
                for (int b = 0; b < 3; b++) bins3[c_l][rb3l][b] += lb3[b];
            }
        }
        __syncthreads();
#pragma unroll
        for (int off = 0; off < 128; off += 64) {
            int px = off + (tid >> 2);
            int chunk = tid & 3;
            if (px < 120) {
                uint4 v = *(const uint4*)(sb + px * 40 + chunk * 8);
                *(uint4*)(d_xnh + ((size_t)(gr + 1) * NHR + (px + 1)) * CCH
                          + cg * 32 + chunk * 8) = v;
            }
        }
        __syncthreads();
    }

    for (int i = tid; i < 320; i += 256) {
        int c_l = i / 10, rem = i % 10, rbl = rem / 5, cb = rem % 5;
        int rb = rbb5 + rbl;
        float v = bins5[c_l][rbl][cb];
        if (rb < 5 && v != 0.f)
            atomicAdd(&d_sum5[(cg * 32 + c_l) * 25 + rb * 5 + cb], v);
    }
    for (int i = tid; i < 192; i += 256) {
        int c_l = i / 6, rem = i % 6, rbl = rem / 3, cb = rem % 3;
        int rb = rbb3 + rbl;
        float v = bins3[c_l][rbl][cb];
        if (rb < 3 && v != 0.f)
            atomicAdd(&d_sum3[(cg * 32 + c_l) * 9 + rb * 3 + cb], v);
    }
}

// ---------------------------------------------------------------------------
// 2) routing net: 48 blocks + spin grid-sync, block 0 tail + scratch reset
// ---------------------------------------------------------------------------
__global__ void route_kernel(const float* __restrict__ w_pw1,
                             const float* __restrict__ w_dw1,
                             const float* __restrict__ w_dw2,
                             const float* __restrict__ w_pw2) {
    const int s = blockIdx.x;
    const int tid = threadIdx.x;

    {
        float acc[25];
#pragma unroll
        for (int pq = 0; pq < 25; pq++) acc[pq] = 0.f;
        for (int ch = tid; ch < 2304; ch += 256) {
            float wv = w_pw1[(size_t)s * 2304 + ch];
            int which = ch / 768;
            int c = ch - which * 768;
            if (which == 0) {
                const float* s5 = d_sum5 + c * 25;
                float tot = 0.f;
#pragma unroll
                for (int j = 0; j < 25; j++) tot += s5[j];
                float v = wv * tot * (1.f / 14400.f);
#pragma unroll
                for (int pq = 0; pq < 25; pq++) acc[pq] += v;
            } else if (which == 1) {
                float s3[9];
#pragma unroll
                for (int j = 0; j < 9; j++)
                    s3[j] = d_sum3[c * 9 + j] * (1.f / 1600.f);
#pragma unroll
                for (int pq = 0; pq < 25; pq++) {
                    int p = pq / 5, q = pq - p * 5;
                    float val = 0.f;
#pragma unroll
                    for (int i = 0; i < 3; i++)
#pragma unroll
                        for (int j = 0; j < 3; j++)
                            val += c_M35[p][i] * c_M35[q][j] * s3[i * 3 + j];
                    acc[pq] += wv * val;
                }
            } else {
                const float* s5 = d_sum5 + c * 25;
#pragma unroll
                for (int pq = 0; pq < 25; pq++)
                    acc[pq] += wv * s5[pq] * (1.f / 576.f);
            }
        }
        __shared__ float red[25][257];
#pragma unroll
        for (int pq = 0; pq < 25; pq++) red[pq][tid] = acc[pq];
        __syncthreads();
        if (tid < 25) {
            float sum = 0.f;
            for (int i = 0; i < 256; i++) sum += red[tid][i];
            d_h1g[s * 25 + tid] = fmaxf(sum, 0.f);
        }
    }
    __threadfence();
    __syncthreads();

    if (s != 0) {
        if (tid == 0) atomicAdd(&d_sync, 1);
        return;
    }
    if (tid == 0) {
        atomicAdd(&d_sync, 1);
        while (atomicAdd(&d_sync, 0) < 48) { }
    }
    __syncthreads();
    __threadfence();

    __shared__ float h1[SQZ * 25];
    __shared__ float h2[SQZ * 9];
    __shared__ float h3[SQZ];
    for (int i = tid; i < SQZ * 25; i += 256) h1[i] = d_h1g[i];
    __syncthreads();

    for (int tsk = tid; tsk < SQZ * 9; tsk += 256) {
        int ss = tsk / 9;
        int r = tsk - ss * 9;
        int p = r / 3, q = r - p * 3;
        float acc = 0.f;
#pragma unroll
        for (int u = 0; u < 3; u++)
#pragma unroll
            for (int v = 0; v < 3; v++)
                acc += h1[ss * 25 + (p + u) * 5 + (q + v)] * w_dw1[ss * 9 + u * 3 + v];
        h2[tsk] = fmaxf(acc, 0.f);
    }
    __syncthreads();

    if (tid < SQZ) {
        float acc = 0.f;
#pragma unroll
        for (int uv = 0; uv < 9; uv++)
            acc += h2[tid * 9 + uv] * w_dw2[tid * 9 + uv];
        h3[tid] = fmaxf(acc, 0.f);
    }
    __syncthreads();

    for (int o = tid; o < 2304; o += 256) {
        const float* wr = w_pw2 + (size_t)o * SQZ;
        float acc = 0.f;
#pragma unroll
        for (int ss = 0; ss < SQZ; ss++) acc += wr[ss] * h3[ss];
        d_route[o] = 1.f / (1.f + expf(-acc));
    }
    for (int i = tid; i < CCH * 25; i += 256) d_sum5[i] = 0.f;
    for (int i = tid; i < CCH * 9; i += 256) d_sum3[i] = 0.f;
    __syncthreads();
    if (tid == 0) d_sync = 0;
}

// ---------------------------------------------------------------------------
// 3) weight synthesis -> fp16 in mma-fragment order
// ---------------------------------------------------------------------------
__global__ void wsyn_kernel(const float* __restrict__ convs) {
    const int oc = blockIdx.x;
    __shared__ float ws[KTOT];
    const int tid = threadIdx.x;

    const float r0 = d_route[oc];
    const float r1 = d_route[768 + oc];
    const float r2 = d_route[1536 + oc];
    const float* c0 = convs + (size_t)oc * KTOT;
    const float* c1 = c0 + (size_t)768 * KTOT;
    const float* c2 = c1 + (size_t)768 * KTOT;

#pragma unroll
    for (int j = 0; j < 27; j++) {
        int i = tid + j * 256;
        ws[i] = r0 * c0[i] + r1 * c1[i] + r2 * c2[i];
    }
    __syncthreads();

    const int g = oc & 7;
    const int rh = (oc >> 3) & 1;
    const int ocb = oc >> 4;
#pragma unroll
    for (int j = 0; j < 27; j++) {
        int idx = tid + j * 256;        // k = tap*768 + ic
        int tap = idx / 768;
        int ic = idx - tap * 768;
        int kb = idx >> 4;
        int kc = idx & 15;
        int t = (kc >> 1) & 3;
        int chalf = kc >> 3;
        int odd = kc & 1;
        int lane = (g << 2) | t;
        int h = chalf * 4 + rh * 2 + odd;
        d_w2f[((((size_t)ocb * 432 + kb) * 32 + lane) << 3) + h] =
            __float2half(ws[ic * 9 + tap]);
    }
}

// ---------------------------------------------------------------------------
// 4) conv GEMM fp16: BM=128, BN=128, BK=64, 128 thr, 2x2 warps (64x64 tiles),
//    occ 2, 3-stage cp.async, NHWC contiguous B gather. 108 iters.
// ---------------------------------------------------------------------------
__device__ __forceinline__ void mma_fp16(float* c, const uint32_t* a, const uint32_t* b) {
    asm volatile(
        "mma.sync.aligned.m16n8k16.row.col.f32.f16.f16.f32 "
        "{%0,%1,%2,%3}, {%4,%5,%6,%7}, {%8,%9}, {%0,%1,%2,%3};\n"
        : "+f"(c[0]), "+f"(c[1]), "+f"(c[2]), "+f"(c[3])
        : "r"(a[0]), "r"(a[1]), "r"(a[2]), "r"(a[3]),
          "r"(b[0]), "r"(b[1]));
}

__device__ __forceinline__ uint32_t cvta_smem(const void* p) {
    uint32_t a;
    asm("{ .reg .u64 t; cvta.to.shared.u64 t, %1; cvt.u32.u64 %0, t; }"
        : "=r"(a) : "l"(p));
    return a;
}

__device__ __forceinline__ void cp16(uint32_t dst, const void* src) {
    asm volatile("cp.async.cg.shared.global [%0], [%1], 16;\n"
                 :: "r"(dst), "l"(src) : "memory");
}

#define ASTG 16384                  // A stage: 1024 chunks * 16B
#define BROW 144                    // B row bytes: 64 halves + 8 pad
#define BSTG (128 * BROW)           // 18432 B
#define SMEM_REQ (3 * (ASTG + BSTG))   // 104448 B

__global__ void __launch_bounds__(128, 2)
conv_gemm_kernel(float* __restrict__ y) {
    extern __shared__ char smraw[];
    char* Abase = smraw;
    char* Bbase = smraw + 3 * ASTG;
    const uint32_t As_u32 = cvta_smem(Abase);
    const uint32_t Bs_u32 = cvta_smem(Bbase);

    const int tid = threadIdx.x;
    const int lane = tid & 31;
    const int g = lane >> 2, t = lane & 3;
    const int warp = tid >> 5;
    const int wm = warp >> 1, wn = warp & 1;   // 2x2 warps, 64x64 tiles
    const int oc0 = blockIdx.y * 128;
    const int ocb0 = blockIdx.y * 8;
    const int n0 = blockIdx.x * 128;

    // B fill: 1024 chunks per stage, 8 per thread; px = (tid>>3) + j*16
    const int pxb = tid >> 3;
    const int bchunk = tid & 7;
    int baseRow[8];
#pragma unroll
    for (int j = 0; j < 8; j++) {
        int pix = n0 + pxb + j * 16;
        int ph = pix / 120;
        int pw = pix - ph * 120;
        baseRow[j] = ph * NHR + pw;
    }

    auto cpA = [&](int it, int st) {
        uint32_t ab = As_u32 + st * ASTG;
#pragma unroll
        for (int j = 0; j < 8; j++) {
            int c = tid + j * 128;
            int ocb_l = c >> 7;
            int rem = c & 127;
            int kbl = rem >> 5;
            int lane_c = rem & 31;
            const __half* src = d_w2f +
                (((size_t)(ocb0 + ocb_l) * 432 + (it * 4 + kbl)) * 32 + lane_c) * 8;
            cp16(ab + c * 16, src);
        }
    };

    auto cpB = [&](int it, int st) {
        int tap = it / 12;
        int ksub = it - tap * 12;
        int du = tap / 3, dv = tap - du * 3;
        int rofs = du * NHR + dv;
        uint32_t bb = Bs_u32 + st * BSTG;
#pragma unroll
        for (int j = 0; j < 8; j++) {
            const __half* src = d_xnh + (size_t)(baseRow[j] + rofs) * CCH
                                + ksub * 64 + bchunk * 8;
            cp16(bb + (pxb + j * 16) * BROW + bchunk * 16, src);
        }
    };

    float acc[4][8][4];
#pragma unroll
    for (int i = 0; i < 4; i++)
#pragma unroll
        for (int j = 0; j < 8; j++)
#pragma unroll
            for (int r = 0; r < 4; r++) acc[i][j][r] = 0.f;

    auto compute = [&](int st) {
        const char* Ab = Abase + st * ASTG;
        const char* Bb = Bbase + st * BSTG;
#pragma unroll
        for (int ks = 0; ks < 4; ++ks) {
            uint4 a[4];
            uint32_t b[8][2];
#pragma unroll
            for (int i = 0; i < 4; i++)
                a[i] = *(const uint4*)(Ab + ((((wm * 4 + i) * 4 + ks) * 32 + lane) << 4));
#pragma unroll
            for (int j = 0; j < 8; j++) {
                int col = wn * 64 + j * 8 + g;
                b[j][0] = *(const uint32_t*)(Bb + col * BROW + ks * 32 + t * 4);
                b[j][1] = *(const uint32_t*)(Bb + col * BROW + ks * 32 + 16 + t * 4);
            }
#pragma unroll
            for (int i = 0; i < 4; i++)
#pragma unroll
                for (int j = 0; j < 8; j++)
                    mma_fp16(acc[i][j], (const uint32_t*)&a[i], b[j]);
        }
    };

    // prologue: stages 0 and 1 in flight
    cpA(0, 0); cpB(0, 0);
    asm volatile("cp.async.commit_group;\n" ::: "memory");
    cpA(1, 1); cpB(1, 1);
    asm volatile("cp.async.commit_group;\n" ::: "memory");
    asm volatile("cp.async.wait_group 1;\n" ::: "memory");
    __syncthreads();

    for (int it = 0; it < NI; ++it) {
        const int st = it % 3;
        const bool more2 = (it + 2) < NI;
        if (more2) {
            int st2 = (it + 2) % 3;
            cpA(it + 2, st2); cpB(it + 2, st2);
            asm volatile("cp.async.commit_group;\n" ::: "memory");
        }
        compute(st);
        if (more2) { asm volatile("cp.async.wait_group 1;\n" ::: "memory"); }
        else       { asm volatile("cp.async.wait_group 0;\n" ::: "memory"); }
        __syncthreads();
    }

    // epilogue
#pragma unroll
    for (int i = 0; i < 4; i++) {
        int oc = oc0 + wm * 64 + i * 16 + g;
        float* y0 = y + (size_t)oc * HW_;
#pragma unroll
        for (int j = 0; j < 8; j++) {
            int pj = n0 + wn * 64 + j * 8 + 2 * t;
            if (pj < HW_) {
                *reinterpret_cast<float2*>(y0 + pj) =
                    make_float2(acc[i][j][0], acc[i][j][1]);
                *reinterpret_cast<float2*>(y0 + (size_t)8 * HW_ + pj) =
                    make_float2(acc[i][j][2], acc[i][j][3]);
            }
        }
    }
}

// ---------------------------------------------------------------------------
extern "C" void kernel_launch(void* const* d_in, const int* in_sizes, int n_in,
                              void* d_out, int out_size) {
    const float* x     = (const float*)d_in[0];
    const float* convs = (const float*)d_in[1];
    const float* w_pw1 = (const float*)d_in[2];
    const float* w_dw1 = (const float*)d_in[3];
    const float* w_dw2 = (const float*)d_in[4];
    const float* w_pw2 = (const float*)d_in[5];
    float* y = (float*)d_out;

    transpool_kernel<<<dim3(24, 12), 256>>>(x);
    route_kernel<<<48, 256>>>(w_pw1, w_dw1, w_dw2, w_pw2);
    wsyn_kernel<<<768, 256>>>(convs);

    cudaFuncSetAttribute(conv_gemm_kernel,
                         cudaFuncAttributeMaxDynamicSharedMemorySize, SMEM_REQ);
    conv_gemm_kernel<<<dim3(113, 6), 128, SMEM_REQ>>>(y);   // 4th launch -> ncu
}

// round 14
// speedup vs baseline: 1.1625x; 1.1625x over previous
#include <cuda_runtime.h>
#include <cuda_fp16.h>
#include <cstdint>

// ---------------------------------------------------------------------------
// DyResConv inference, batch=1 — fp16 mma.sync m16n8k16 implicit GEMM
//   GEMM: C[768 x 14400] = W2[768 x 6912] * im2col(x),  k = tap*768 + ic
// R14: mbarrier producer/consumer ring (no __syncthreads in mainloop);
//      3 stages, BK=64, 128 thr, 2x2 warps (64x64 tiles), occ 2.
// ---------------------------------------------------------------------------

#define CCH 768
#define SQZ 48
#define HW_ 14400
#define KTOT 6912
#define NI   108            // 6912 / 64
#define NHR  122
#define NHPL (NHR * NHR)

// scratch (device globals; no allocation allowed)
__device__ float d_sum5[CCH * 25];
__device__ float d_sum3[CCH * 9];
__device__ float d_route[2304];
__device__ float d_h1g[SQZ * 25];
__device__ int   d_sync;
__device__ __half d_w2f[CCH * KTOT];          // weights in mma-fragment order
__device__ __half d_xnh[(size_t)NHPL * CCH];  // padded x, NHWC halves

__constant__ float c_M35[5][3] = {
    { 1.096f, -0.096f,  0.000f},
    { 0.612f,  0.460f, -0.072f},
    { 0.000f,  1.000f,  0.000f},
    {-0.072f,  0.460f,  0.612f},
    { 0.000f, -0.096f,  1.096f}
};

// ---------------------------------------------------------------------------
// 1) fused transpose (NCHW f32 -> padded NHWC f16) + pooling via shfl trees.
// ---------------------------------------------------------------------------
__global__ void transpool_kernel(const float* __restrict__ x) {
    const int cg = blockIdx.x;
    const int pg = blockIdx.y;
    const int tid = threadIdx.x;
    const int warp = tid >> 5, lane = tid & 31;
    const int r0 = pg * 10;

    __shared__ __half sb[120 * 40];
    __shared__ float bins5[32][2][5];
    __shared__ float bins3[32][2][3];

    for (int i = tid; i < 32 * 10; i += 256) bins5[i / 10][(i % 10) / 5][i % 5] = 0.f;
    for (int i = tid; i < 32 * 6; i += 256) bins3[i / 6][(i % 6) / 3][i % 3] = 0.f;

    {
        int id = pg * 256 + tid;
        if (id < 484 * 4) {
            int b = id >> 2, chunk = id & 3;
            int prow, pcol;
            if (b < 122)      { prow = 0;        pcol = b; }
            else if (b < 244) { prow = 121;      pcol = b - 122; }
            else if (b < 364) { prow = b - 243;  pcol = 0; }
            else              { prow = b - 363;  pcol = 121; }
            *(uint4*)(d_xnh + ((size_t)prow * NHR + pcol) * CCH + cg * 32 + chunk * 8) =
                make_uint4(0u, 0u, 0u, 0u);
        }
    }
    __syncthreads();

    const int rbb5 = r0 / 24, rbb3 = r0 / 40;

    for (int r = 0; r < 10; r++) {
        const int gr = r0 + r;
        const int rb5l = gr / 24 - rbb5;
        const int rb3l = gr / 40 - rbb3;
#pragma unroll
        for (int cidx = 0; cidx < 4; cidx++) {
            int c_l = warp + cidx * 8;
            const float* xr = x + (size_t)(cg * 32 + c_l) * HW_ + gr * 120;
            float lb5[5] = {0.f, 0.f, 0.f, 0.f, 0.f};
            float lb3[3] = {0.f, 0.f, 0.f};
#pragma unroll
            for (int k = 0; k < 4; k++) {
                int px = lane + k * 32;
                if (px < 120) {
                    float v = xr[px];
                    sb[px * 40 + c_l] = __float2half(v);
                    lb5[px / 24] += v;
                    lb3[px / 40] += v;
                }
            }
#pragma unroll
            for (int o = 16; o > 0; o >>= 1) {
#pragma unroll
                for (int b = 0; b < 5; b++)
                    lb5[b] += __shfl_down_sync(0xFFFFFFFFu, lb5[b], o);
#pragma unroll
                for (int b = 0; b < 3; b++)
                    lb3[b] += __shfl_down_sync(0xFFFFFFFFu, lb3[b], o);
            }
            if (lane == 0) {
#pragma unroll
                for (int b = 0; b < 5; b++) bins5[c_l][rb5l][b] += lb5[b];
#pragma unroll
                for (int b = 0; b < 3; b++) bins3[c_l][rb3l][b] += lb3[b];
            }
        }
        __syncthreads();
#pragma unroll
        for (int off = 0; off < 128; off += 64) {
            int px = off + (tid >> 2);
            int chunk = tid & 3;
            if (px < 120) {
                uint4 v = *(const uint4*)(sb + px * 40 + chunk * 8);
                *(uint4*)(d_xnh + ((size_t)(gr + 1) * NHR + (px + 1)) * CCH
                          + cg * 32 + chunk * 8) = v;
            }
        }
        __syncthreads();
    }

    for (int i = tid; i < 320; i += 256) {
        int c_l = i / 10, rem = i % 10, rbl = rem / 5, cb = rem % 5;
        int rb = rbb5 + rbl;
        float v = bins5[c_l][rbl][cb];
        if (rb < 5 && v != 0.f)
            atomicAdd(&d_sum5[(cg * 32 + c_l) * 25 + rb * 5 + cb], v);
    }
    for (int i = tid; i < 192; i += 256) {
        int c_l = i / 6, rem = i % 6, rbl = rem / 3, cb = rem % 3;
        int rb = rbb3 + rbl;
        float v = bins3[c_l][rbl][cb];
        if (rb < 3 && v != 0.f)
            atomicAdd(&d_sum3[(cg * 32 + c_l) * 9 + rb * 3 + cb], v);
    }
}

// ---------------------------------------------------------------------------
// 2) routing net: 48 blocks + spin grid-sync, block 0 tail + scratch reset
// ---------------------------------------------------------------------------
__global__ void route_kernel(const float* __restrict__ w_pw1,
                             const float* __restrict__ w_dw1,
                             const float* __restrict__ w_dw2,
                             const float* __restrict__ w_pw2) {
    const int s = blockIdx.x;
    const int tid = threadIdx.x;

    {
        float acc[25];
#pragma unroll
        for (int pq = 0; pq < 25; pq++) acc[pq] = 0.f;
        for (int ch = tid; ch < 2304; ch += 256) {
            float wv = w_pw1[(size_t)s * 2304 + ch];
            int which = ch / 768;
            int c = ch - which * 768;
            if (which == 0) {
                const float* s5 = d_sum5 + c * 25;
                float tot = 0.f;
#pragma unroll
                for (int j = 0; j < 25; j++) tot += s5[j];
                float v = wv * tot * (1.f / 14400.f);
#pragma unroll
                for (int pq = 0; pq < 25; pq++) acc[pq] += v;
            } else if (which == 1) {
                float s3[9];
#pragma unroll
                for (int j = 0; j < 9; j++)
                    s3[j] = d_sum3[c * 9 + j] * (1.f / 1600.f);
#pragma unroll
                for (int pq = 0; pq < 25; pq++) {
                    int p = pq / 5, q = pq - p * 5;
                    float val = 0.f;
#pragma unroll
                    for (int i = 0; i < 3; i++)
#pragma unroll
                        for (int j = 0; j < 3; j++)
                            val += c_M35[p][i] * c_M35[q][j] * s3[i * 3 + j];
                    acc[pq] += wv * val;
                }
            } else {
                const float* s5 = d_sum5 + c * 25;
#pragma unroll
                for (int pq = 0; pq < 25; pq++)
                    acc[pq] += wv * s5[pq] * (1.f / 576.f);
            }
        }
        __shared__ float red[25][257];
#pragma unroll
        for (int pq = 0; pq < 25; pq++) red[pq][tid] = acc[pq];
        __syncthreads();
        if (tid < 25) {
            float sum = 0.f;
            for (int i = 0; i < 256; i++) sum += red[tid][i];
            d_h1g[s * 25 + tid] = fmaxf(sum, 0.f);
        }
    }
    __threadfence();
    __syncthreads();

    if (s != 0) {
        if (tid == 0) atomicAdd(&d_sync, 1);
        return;
    }
    if (tid == 0) {
        atomicAdd(&d_sync, 1);
        while (atomicAdd(&d_sync, 0) < 48) { }
    }
    __syncthreads();
    __threadfence();

    __shared__ float h1[SQZ * 25];
    __shared__ float h2[SQZ * 9];
    __shared__ float h3[SQZ];
    for (int i = tid; i < SQZ * 25; i += 256) h1[i] = d_h1g[i];
    __syncthreads();

    for (int tsk = tid; tsk < SQZ * 9; tsk += 256) {
        int ss = tsk / 9;
        int r = tsk - ss * 9;
        int p = r / 3, q = r - p * 3;
        float acc = 0.f;
#pragma unroll
        for (int u = 0; u < 3; u++)
#pragma unroll
            for (int v = 0; v < 3; v++)
                acc += h1[ss * 25 + (p + u) * 5 + (q + v)] * w_dw1[ss * 9 + u * 3 + v];
        h2[tsk] = fmaxf(acc, 0.f);
    }
    __syncthreads();

    if (tid < SQZ) {
        float acc = 0.f;
#pragma unroll
        for (int uv = 0; uv < 9; uv++)
            acc += h2[tid * 9 + uv] * w_dw2[tid * 9 + uv];
        h3[tid] = fmaxf(acc, 0.f);
    }
    __syncthreads();

    for (int o = tid; o < 2304; o += 256) {
        const float* wr = w_pw2 + (size_t)o * SQZ;
        float acc = 0.f;
#pragma unroll
        for (int ss = 0; ss < SQZ; ss++) acc += wr[ss] * h3[ss];
        d_route[o] = 1.f / (1.f + expf(-acc));
    }
    for (int i = tid; i < CCH * 25; i += 256) d_sum5[i] = 0.f;
    for (int i = tid; i < CCH * 9; i += 256) d_sum3[i] = 0.f;
    __syncthreads();
    if (tid == 0) d_sync = 0;
}

// ---------------------------------------------------------------------------
// 3) weight synthesis -> fp16 in mma-fragment order
// ---------------------------------------------------------------------------
__global__ void wsyn_kernel(const float* __restrict__ convs) {
    const int oc = blockIdx.x;
    __shared__ float ws[KTOT];
    const int tid = threadIdx.x;

    const float r0 = d_route[oc];
    const float r1 = d_route[768 + oc];
    const float r2 = d_route[1536 + oc];
    const float* c0 = convs + (size_t)oc * KTOT;
    const float* c1 = c0 + (size_t)768 * KTOT;
    const float* c2 = c1 + (size_t)768 * KTOT;

#pragma unroll
    for (int j = 0; j < 27; j++) {
        int i = tid + j * 256;
        ws[i] = r0 * c0[i] + r1 * c1[i] + r2 * c2[i];
    }
    __syncthreads();

    const int g = oc & 7;
    const int rh = (oc >> 3) & 1;
    const int ocb = oc >> 4;
#pragma unroll
    for (int j = 0; j < 27; j++) {
        int idx = tid + j * 256;        // k = tap*768 + ic
        int tap = idx / 768;
        int ic = idx - tap * 768;
        int kb = idx >> 4;
        int kc = idx & 15;
        int t = (kc >> 1) & 3;
        int chalf = kc >> 3;
        int odd = kc & 1;
        int lane = (g << 2) | t;
        int h = chalf * 4 + rh * 2 + odd;
        d_w2f[((((size_t)ocb * 432 + kb) * 32 + lane) << 3) + h] =
            __float2half(ws[ic * 9 + tap]);
    }
}

// ---------------------------------------------------------------------------
// 4) conv GEMM fp16 with mbarrier producer/consumer ring.
//    BM=128, BN=128, BK=64, 128 thr, 2x2 warps (64x64 tiles), occ 2.
// ---------------------------------------------------------------------------
__device__ __forceinline__ void mma_fp16(float* c, const uint32_t* a, const uint32_t* b) {
    asm volatile(
        "mma.sync.aligned.m16n8k16.row.col.f32.f16.f16.f32 "
        "{%0,%1,%2,%3}, {%4,%5,%6,%7}, {%8,%9}, {%0,%1,%2,%3};\n"
        : "+f"(c[0]), "+f"(c[1]), "+f"(c[2]), "+f"(c[3])
        : "r"(a[0]), "r"(a[1]), "r"(a[2]), "r"(a[3]),
          "r"(b[0]), "r"(b[1]));
}

__device__ __forceinline__ uint32_t cvta_smem(const void* p) {
    uint32_t a;
    asm("{ .reg .u64 t; cvta.to.shared.u64 t, %1; cvt.u32.u64 %0, t; }"
        : "=r"(a) : "l"(p));
    return a;
}

__device__ __forceinline__ void cp16(uint32_t dst, const void* src) {
    asm volatile("cp.async.cg.shared.global [%0], [%1], 16;\n"
                 :: "r"(dst), "l"(src) : "memory");
}

// spin on phase parity: succeeds when current phase parity != par
__device__ __forceinline__ void mbar_wait(uint32_t mbar, uint32_t par) {
    uint32_t done;
    asm volatile(
        "{\n\t.reg .pred p;\n\t"
        "mbarrier.try_wait.parity.acquire.cta.shared::cta.b64 p, [%1], %2;\n\t"
        "selp.b32 %0, 1, 0, p;\n\t}"
        : "=r"(done) : "r"(mbar), "r"(par) : "memory");
    while (!done) {
        asm volatile(
            "{\n\t.reg .pred p;\n\t"
            "mbarrier.try_wait.parity.acquire.cta.shared::cta.b64 p, [%1], %2, 0x989680;\n\t"
            "selp.b32 %0, 1, 0, p;\n\t}"
            : "=r"(done) : "r"(mbar), "r"(par) : "memory");
    }
}

#define ASTG 16384                  // A stage: 1024 chunks * 16B
#define BROW 144                    // B row bytes: 64 halves + 8 pad
#define BSTG (128 * BROW)           // 18432 B
#define STAGE_B (ASTG + BSTG)       // 34816 B
#define SMEM_REQ (3 * STAGE_B + 128)   // 104576 B

__global__ void __launch_bounds__(128, 2)
conv_gemm_kernel(float* __restrict__ y) {
    extern __shared__ char smraw[];
    const uint32_t mb = cvta_smem(smraw);        // mbarriers in [0,48)
    char* Tbase = smraw + 128;
    const uint32_t T_u32 = mb + 128;

    const int tid = threadIdx.x;
    const int lane = tid & 31;
    const int g = lane >> 2, t = lane & 3;
    const int warp = tid >> 5;
    const int wm = warp >> 1, wn = warp & 1;     // 2x2 warps, 64x64 tiles
    const int oc0 = blockIdx.y * 128;
    const int ocb0 = blockIdx.y * 8;
    const int n0 = blockIdx.x * 128;

    // full[st] = mb + st*16, empty[st] = mb + st*16 + 8
    if (tid == 0) {
#pragma unroll
        for (int s = 0; s < 3; s++) {
            asm volatile("mbarrier.init.shared.b64 [%0], 128;"
                         :: "r"(mb + s * 16) : "memory");
            asm volatile("mbarrier.init.shared.b64 [%0], 128;"
                         :: "r"(mb + s * 16 + 8) : "memory");
        }
    }
    __syncthreads();

    // B fill geometry
    const int pxb = tid >> 3;
    const int bchunk = tid & 7;
    int baseRow[8];
#pragma unroll
    for (int j = 0; j < 8; j++) {
        int pix = n0 + pxb + j * 16;
        int ph = pix / 120;
        int pw = pix - ph * 120;
        baseRow[j] = ph * NHR + pw;
    }

    auto produce = [&](int it, uint32_t pph) {
        const int st = it % 3;
        mbar_wait(mb + st * 16 + 8, pph);        // wait empty(st)
        uint32_t ab = T_u32 + st * STAGE_B;
#pragma unroll
        for (int j = 0; j < 8; j++) {
            int c = tid + j * 128;
            int ocb_l = c >> 7;
            int rem = c & 127;
            int kbl = rem >> 5;
            int lane_c = rem & 31;
            const __half* src = d_w2f +
                (((size_t)(ocb0 + ocb_l) * 432 + (it * 4 + kbl)) * 32 + lane_c) * 8;
            cp16(ab + c * 16, src);
        }
        int tap = it / 12;
        int ksub = it - tap * 12;
        int du = tap / 3, dv = tap - du * 3;
        int rofs = du * NHR + dv;
        uint32_t bb = T_u32 + st * STAGE_B + ASTG;
#pragma unroll
        for (int j = 0; j < 8; j++) {
            const __half* src = d_xnh + (size_t)(baseRow[j] + rofs) * CCH
                                + ksub * 64 + bchunk * 8;
            cp16(bb + (pxb + j * 16) * BROW + bchunk * 16, src);
        }
        asm volatile("cp.async.mbarrier.arrive.noinc.shared.b64 [%0];"
                     :: "r"(mb + st * 16) : "memory");   // arrive full(st) on completion
    };

    float acc[4][8][4];
#pragma unroll
    for (int i = 0; i < 4; i++)
#pragma unroll
        for (int j = 0; j < 8; j++)
#pragma unroll
            for (int r = 0; r < 4; r++) acc[i][j][r] = 0.f;

    auto compute = [&](int st) {
        const char* Ab = Tbase + st * STAGE_B;
        const char* Bb = Ab + ASTG;
#pragma unroll
        for (int ks = 0; ks < 4; ++ks) {
            uint4 a[4];
            uint32_t b[8][2];
#pragma unroll
            for (int i = 0; i < 4; i++)
                a[i] = *(const uint4*)(Ab + ((((wm * 4 + i) * 4 + ks) * 32 + lane) << 4));
#pragma unroll
            for (int j = 0; j < 8; j++) {
                int col = wn * 64 + j * 8 + g;
                b[j][0] = *(const uint32_t*)(Bb + col * BROW + ks * 32 + t * 4);
                b[j][1] = *(const uint32_t*)(Bb + col * BROW + ks * 32 + 16 + t * 4);
            }
#pragma unroll
            for (int i = 0; i < 4; i++)
#pragma unroll
                for (int j = 0; j < 8; j++)
                    mma_fp16(acc[i][j], (const uint32_t*)&a[i], b[j]);
        }
    };

    // prologue: fill all 3 stages (producer phase starts at parity 1)
    produce(0, 1);
    produce(1, 1);
    produce(2, 1);
    uint32_t p_ph = 0;                  // next producer round wraps -> parity 0
    uint32_t c_ph = 0;                  // consumer starts at parity 0

    for (int it = 0; it < NI; ++it) {
        const int st = it % 3;
        mbar_wait(mb + st * 16, c_ph);             // wait full(st)
        compute(st);
        asm volatile(
            "{ .reg .b64 tk; mbarrier.arrive.shared.b64 tk, [%0]; }"
            :: "r"(mb + st * 16 + 8) : "memory");  // arrive empty(st)
        if (st == 2) c_ph ^= 1;
        const int nx = it + 3;
        if (nx < NI) {
            produce(nx, p_ph);
            if (nx % 3 == 2) p_ph ^= 1;
        }
    }

    // epilogue (per-warp private accumulators; no further sync needed)
#pragma unroll
    for (int i = 0; i < 4; i++) {
        int oc = oc0 + wm * 64 + i * 16 + g;
        float* y0 = y + (size_t)oc * HW_;
#pragma unroll
        for (int j = 0; j < 8; j++) {
            int pj = n0 + wn * 64 + j * 8 + 2 * t;
            if (pj < HW_) {
                *reinterpret_cast<float2*>(y0 + pj) =
                    make_float2(acc[i][j][0], acc[i][j][1]);
                *reinterpret_cast<float2*>(y0 + (size_t)8 * HW_ + pj) =
                    make_float2(acc[i][j][2], acc[i][j][3]);
            }
        }
    }
}

// ---------------------------------------------------------------------------
extern "C" void kernel_launch(void* const* d_in, const int* in_sizes, int n_in,
                              void* d_out, int out_size) {
    const float* x     = (const float*)d_in[0];
    const float* convs = (const float*)d_in[1];
    const float* w_pw1 = (const float*)d_in[2];
    const float* w_dw1 = (const float*)d_in[3];
    const float* w_dw2 = (const float*)d_in[4];
    const float* w_pw2 = (const float*)d_in[5];
    float* y = (float*)d_out;

    transpool_kernel<<<dim3(24, 12), 256>>>(x);
    route_kernel<<<48, 256>>>(w_pw1, w_dw1, w_dw2, w_pw2);
    wsyn_kernel<<<768, 256>>>(convs);

    cudaFuncSetAttribute(conv_gemm_kernel,
                         cudaFuncAttributeMaxDynamicSharedMemorySize, SMEM_REQ);
    conv_gemm_kernel<<<dim3(113, 6), 128, SMEM_REQ>>>(y);   // 4th launch -> ncu
}